// round 3
// baseline (speedup 1.0000x reference)
#include <cuda_runtime.h>

#define NBLK 4096
#define NTHR 256

// Device scratch (no cudaMalloc allowed). g_count is zero at module load and
// self-resets via atomicInc wrap, so the kernel is replay-deterministic.
__device__ float g_part[NBLK];
__device__ unsigned int g_count;

__global__ void __launch_bounds__(NTHR)
mse_kernel(const float* __restrict__ in,
           const float* __restrict__ tg,
           float* __restrict__ out,
           int n) {
    const float4* __restrict__ in4 = (const float4*)in;
    const float4* __restrict__ tg4 = (const float4*)tg;
    const int n4 = n >> 2;

    const int stride = NBLK * NTHR;
    int i = blockIdx.x * NTHR + threadIdx.x;

    float acc0 = 0.0f, acc1 = 0.0f;

    // Unrolled ×4: 8 independent LDG.128 in flight per iteration.
    for (; i + 3 * stride < n4; i += 4 * stride) {
        float4 a0 = __ldg(&in4[i]);
        float4 a1 = __ldg(&in4[i + stride]);
        float4 a2 = __ldg(&in4[i + 2 * stride]);
        float4 a3 = __ldg(&in4[i + 3 * stride]);
        float4 b0 = __ldg(&tg4[i]);
        float4 b1 = __ldg(&tg4[i + stride]);
        float4 b2 = __ldg(&tg4[i + 2 * stride]);
        float4 b3 = __ldg(&tg4[i + 3 * stride]);

        float d;
        d = a0.x - b0.x; acc0 = fmaf(d, d, acc0);
        d = a0.y - b0.y; acc1 = fmaf(d, d, acc1);
        d = a0.z - b0.z; acc0 = fmaf(d, d, acc0);
        d = a0.w - b0.w; acc1 = fmaf(d, d, acc1);
        d = a1.x - b1.x; acc0 = fmaf(d, d, acc0);
        d = a1.y - b1.y; acc1 = fmaf(d, d, acc1);
        d = a1.z - b1.z; acc0 = fmaf(d, d, acc0);
        d = a1.w - b1.w; acc1 = fmaf(d, d, acc1);
        d = a2.x - b2.x; acc0 = fmaf(d, d, acc0);
        d = a2.y - b2.y; acc1 = fmaf(d, d, acc1);
        d = a2.z - b2.z; acc0 = fmaf(d, d, acc0);
        d = a2.w - b2.w; acc1 = fmaf(d, d, acc1);
        d = a3.x - b3.x; acc0 = fmaf(d, d, acc0);
        d = a3.y - b3.y; acc1 = fmaf(d, d, acc1);
        d = a3.z - b3.z; acc0 = fmaf(d, d, acc0);
        d = a3.w - b3.w; acc1 = fmaf(d, d, acc1);
    }
    // Tail (runs 0 times for N = 32M with this grid, but keep it general).
    for (; i < n4; i += stride) {
        float4 a = __ldg(&in4[i]);
        float4 b = __ldg(&tg4[i]);
        float d;
        d = a.x - b.x; acc0 = fmaf(d, d, acc0);
        d = a.y - b.y; acc1 = fmaf(d, d, acc1);
        d = a.z - b.z; acc0 = fmaf(d, d, acc0);
        d = a.w - b.w; acc1 = fmaf(d, d, acc1);
    }

    float acc = acc0 + acc1;

    // Warp reduction
    #pragma unroll
    for (int off = 16; off > 0; off >>= 1)
        acc += __shfl_xor_sync(0xFFFFFFFFu, acc, off);

    __shared__ float warp_sums[NTHR / 32];
    int lane = threadIdx.x & 31;
    int wid  = threadIdx.x >> 5;
    if (lane == 0) warp_sums[wid] = acc;
    __syncthreads();

    __shared__ bool is_last;
    if (wid == 0) {
        float v = (lane < NTHR / 32) ? warp_sums[lane] : 0.0f;
        #pragma unroll
        for (int off = 16; off > 0; off >>= 1)
            v += __shfl_xor_sync(0xFFFFFFFFu, v, off);
        if (lane == 0) {
            g_part[blockIdx.x] = v;
            __threadfence();
            // Wraps back to 0 after the last block -> replay-deterministic.
            unsigned old = atomicInc(&g_count, NBLK - 1);
            is_last = (old == NBLK - 1);
        }
    }
    __syncthreads();

    if (!is_last) return;

    // ── Last block: reduce the 4096 partials in double + finalize ──
    __threadfence();  // acquire: make all blocks' g_part writes visible

    double s = 0.0;
    for (int k = threadIdx.x; k < NBLK; k += NTHR)
        s += (double)g_part[k];

    #pragma unroll
    for (int off = 16; off > 0; off >>= 1)
        s += __shfl_xor_sync(0xFFFFFFFFu, s, off);

    __shared__ double dsums[NTHR / 32];
    if (lane == 0) dsums[wid] = s;
    __syncthreads();

    if (threadIdx.x == 0) {
        double total = 0.0;
        #pragma unroll
        for (int w = 0; w < NTHR / 32; w++) total += dsums[w];

        // Element-0 conditional rescale, applied analytically.
        float d0 = fabsf(in[0] - tg[0]);
        bool hit = (d0 == 3.0f) || (d0 == 4.0f) || (d0 == 5.0f) || (d0 == 6.0f);
        float d0a = hit ? d0 * 0.8f : d0;
        total += (double)d0a * (double)d0a - (double)d0 * (double)d0;

        out[0] = (float)(total / (double)n);
    }
}

extern "C" void kernel_launch(void* const* d_in, const int* in_sizes, int n_in,
                              void* d_out, int out_size) {
    const float* in = (const float*)d_in[0];
    const float* tg = (const float*)d_in[1];
    float* out = (float*)d_out;
    int n = in_sizes[0];

    mse_kernel<<<NBLK, NTHR>>>(in, tg, out, n);
}